// round 15
// baseline (speedup 1.0000x reference)
#include <cuda_runtime.h>
#include <cuda_fp16.h>
#include <math.h>
#include <stdint.h>

// Problem constants
#define BB   64
#define TT   30
#define SS   100
#define HH   256
#define ROWS (BB*TT)      // 1920
#define VV   50000
#define NTILE 391         // ceil(50000/128)

// -------- device scratch --------
__device__ float    g_cat [ROWS*768];              // only dec section used now
__device__ uint32_t g_Ah  [ROWS*128];
__device__ uint32_t g_Al  [ROWS*128];
__device__ uint32_t g_W2h [(size_t)VV*128];
__device__ uint32_t g_W2l [(size_t)VV*128];
__device__ uint32_t g_C16 [(size_t)ROWS*(VV/2)];   // logits as half2 (192MB)
__device__ float    g_Wiht[HH*768];
__device__ float    g_Whht[HH*768];
__device__ float    g_W1t [768*HH];
__device__ float    g_pm  [(size_t)ROWS*NTILE];
__device__ float    g_ps  [(size_t)ROWS*NTILE];
__device__ int      g_pi  [(size_t)ROWS*NTILE];

__device__ __forceinline__ float sigm(float x){ return 1.f/(1.f+expf(-x)); }

// fast e^x (poly exp2, ~3e-8 rel)
__device__ __forceinline__ float fexp(float x){
    float y = x * 1.44269504088896341f;
    float z = y + 12582912.0f;
    int   n = __float_as_int(z);
    float f = y - (z - 12582912.0f);
    float p =              1.53386992e-4f;
    p = fmaf(p, f,         1.33335581e-3f);
    p = fmaf(p, f,         9.61812911e-3f);
    p = fmaf(p, f,         5.55041087e-2f);
    p = fmaf(p, f,         2.40226507e-1f);
    p = fmaf(p, f,         6.93147181e-1f);
    p = fmaf(p, f,         1.0f);
    return __int_as_float(__float_as_int(p) + (n << 23));
}
__device__ __forceinline__ float fexps(float x){
    return (x < -80.f) ? 0.f : fexp(x);
}

__device__ __forceinline__ void split2(float f0, float f1, uint32_t& hi, uint32_t& lo){
    half h0 = __float2half_rn(f0);
    half h1 = __float2half_rn(f1);
    half l0 = __float2half_rn(f0 - __half2float(h0));
    half l1 = __float2half_rn(f1 - __half2float(h1));
    half2 H = __halves2half2(h0, h1);
    half2 L = __halves2half2(l0, l1);
    hi = *(uint32_t*)&H;
    lo = *(uint32_t*)&L;
}

__device__ __forceinline__ uint32_t smem_u32(const void* p){
    uint32_t a;
    asm("{ .reg .u64 t; cvta.to.shared.u64 t, %1; cvt.u32.u64 %0, t; }" : "=r"(a) : "l"(p));
    return a;
}

// W2 split work distributed into small kernels' tail blocks.
#define QTOT 3200000L
__device__ void w2split_quads(const float* __restrict__ W2,
                              long q0, long q1, int bid, int nb)
{
    const long stride = (long)nb * 256;
    for (long q = q0 + (long)bid*256 + threadIdx.x; q < q1; q += stride){
        float4 f = ((const float4*)W2)[q];
        uint32_t h0, l0, h1, l1;
        split2(f.x, f.y, h0, l0);
        split2(f.z, f.w, h1, l1);
        *(uint2*)&g_W2h[q*2] = make_uint2(h0, h1);
        *(uint2*)&g_W2l[q*2] = make_uint2(l0, l1);
    }
}
#define QD0 0L
#define QD1 753000L

#define MMA16(d, a, b) asm volatile( \
 "mma.sync.aligned.m16n8k16.row.col.f32.f16.f16.f32 " \
 "{%0,%1,%2,%3}, {%4,%5,%6,%7}, {%8,%9}, {%0,%1,%2,%3};" \
 : "+f"((d)[0]), "+f"((d)[1]), "+f"((d)[2]), "+f"((d)[3]) \
 : "r"((a)[0]), "r"((a)[1]), "r"((a)[2]), "r"((a)[3]), "r"((b)[0]), "r"((b)[1]))

#define LDSM4(r, addr) asm volatile( \
 "ldmatrix.sync.aligned.m8n8.x4.shared.b16 {%0,%1,%2,%3}, [%4];" \
 : "=r"((r)[0]), "=r"((r)[1]), "=r"((r)[2]), "=r"((r)[3]) : "r"(addr))

#define CP16(dst, src) asm volatile( \
 "cp.async.ca.shared.global [%0], [%1], 16;" :: "r"(dst), "l"(src) : "memory")
#define CP_COMMIT() asm volatile("cp.async.commit_group;" ::: "memory")
#define CP_WAIT1()  asm volatile("cp.async.wait_group 1;" ::: "memory")

// ---------------------------------------------------------
// K0: weight transposes only
// ---------------------------------------------------------
#define NW (768*256)
__global__ void k_prep(const float* __restrict__ Wih,
                       const float* __restrict__ Whh,
                       const float* __restrict__ W1)
{
    int idx = blockIdx.x*blockDim.x + threadIdx.x;
    if (idx < NW){
        int k = idx/768, c = idx%768;
        g_Wiht[idx] = Wih[c*256 + k];
    } else if (idx < 2*NW){
        int j = idx - NW; int k = j/768, c = j%768;
        g_Whht[j] = Whh[c*256 + k];
    } else if (idx < 3*NW){
        int j = idx - 2*NW; int i = j/256, o = j%256;
        g_W1t[j] = W1[o*768 + i];
    }
}

// ---------------------------------------------------------
// K1: GRU decode   grid (3, 64, 2); z=1 blocks do W2 split
// ---------------------------------------------------------
__global__ __launch_bounds__(256) void k_dec(const int*   __restrict__ ci,
                                             const float* __restrict__ hc,
                                             const float* __restrict__ wemb,
                                             const float* __restrict__ bih,
                                             const float* __restrict__ bhh,
                                             const float* __restrict__ W2)
{
    if (blockIdx.z == 1){
        w2split_quads(W2, QD0, QD1, blockIdx.y*3 + blockIdx.x, 3*BB);
        return;
    }
    __shared__ float h0s[256];
    __shared__ float embs[10*256];
    const int b  = blockIdx.y;
    const int tg = blockIdx.x;
    const int j  = threadIdx.x;

    h0s[j] = hc[b*256 + j];
    for (int i = j; i < 10*256; i += 256){
        int r = i >> 8, k = i & 255;
        int tok = ci[b*TT + tg*10 + r];
        embs[i] = wemb[(size_t)tok*256 + k];
    }
    __syncthreads();

    float ghr = bhh[j], ghz = bhh[256+j], ghn = bhh[512+j];
    for (int k = 0; k < 256; k++){
        float hv = h0s[k];
        ghr += g_Whht[k*768 +       j]*hv;
        ghz += g_Whht[k*768 + 256 + j]*hv;
        ghn += g_Whht[k*768 + 512 + j]*hv;
    }

    float aR[10], aZ[10], aN[10];
    #pragma unroll
    for (int r=0;r<10;r++){ aR[r]=0.f; aZ[r]=0.f; aN[r]=0.f; }
    for (int k = 0; k < 256; k++){
        float wr = g_Wiht[k*768 +       j];
        float wz = g_Wiht[k*768 + 256 + j];
        float wn = g_Wiht[k*768 + 512 + j];
        #pragma unroll
        for (int r=0;r<10;r++){
            float e = embs[r*256 + k];
            aR[r] += wr*e; aZ[r] += wz*e; aN[r] += wn*e;
        }
    }
    const float bR = bih[j], bZ = bih[256+j], bN = bih[512+j];
    const float h0v = h0s[j];
    #pragma unroll
    for (int r=0;r<10;r++){
        float rr  = sigm(aR[r] + bR + ghr);
        float zz  = sigm(aZ[r] + bZ + ghz);
        float nn  = tanhf(aN[r] + bN + rr*ghn);
        float dec = (1.f - zz)*nn + zz*h0v;
        int row = b*TT + tg*10 + r;
        g_cat[(size_t)row*768 + 256 + j] = dec;
    }
}

// ---------------------------------------------------------
// K2: FUSED dual attention + hidden layer.
//     grid (6, 64, 2); z=1 blocks do the remaining W2 split.
//     Each z=0 block: 5 timesteps of one batch ->
//       phase 1-3: attention (ctx/ast built in smem cat)
//       phase 4:   hid = relu(cat @ W1^T + b1), W1t streamed
//                  via 3-stage cp.async ring (prefetch issued
//                  BEFORE attention so W1 arrives for free)
//       phase 5:   fp16 hi/lo split -> g_Ah / g_Al
// ---------------------------------------------------------
#define TA 5
#define HCH 96
__global__ __launch_bounds__(256) void k_attn_hid(const float* __restrict__ tok,
                                                  const float* __restrict__ ast,
                                                  const float* __restrict__ b1,
                                                  const float* __restrict__ W2)
{
    if (blockIdx.z == 1){
        w2split_quads(W2, QD1, QTOT, blockIdx.y*6 + blockIdx.x, 6*BB);
        return;
    }
    __shared__ float cat[TA*768];          // [ctx | dec | ast]  15.4KB
    __shared__ float as_[2*TA*100];        // 4KB
    __shared__ float w1s[3][8*256];        // 24KB
    const int b  = blockIdx.y;
    const int tg = blockIdx.x;
    const int tid = threadIdx.x;
    const int t0 = tg*TA;

    // ---- W1 cp.async prologue (overlaps with attention) ----
    uint32_t w1dst[2];
    const float* w1src[2];
    #pragma unroll
    for (int it = 0; it < 2; it++){
        int seg = it*256 + tid;
        int row = seg >> 6;
        int col4 = (seg & 63) * 4;
        w1dst[it] = smem_u32(&w1s[0][row*256 + col4]);
        w1src[it] = g_W1t + row*256 + col4;
    }
    #pragma unroll
    for (int c = 0; c < 2; c++){
        CP16(w1dst[0] + c*8192, w1src[0] + c*2048);
        CP16(w1dst[1] + c*8192, w1src[1] + c*2048);
        CP_COMMIT();
    }

    // ---- load dec rows into cat middle section ----
    for (int i = tid; i < TA*256; i += 256){
        int t = i >> 8, h = i & 255;
        cat[t*768 + 256 + h] = g_cat[(size_t)(b*TT + t0 + t)*768 + 256 + h];
    }
    __syncthreads();

    const size_t base = (size_t)b * (SS*HH);

    // ---- phase 1: scores (raw-reshape keys!) ----
    if (tid < 200){
        const int e = tid / 100;
        const int s = tid % 100;
        const float* enc = e ? ast : tok;
        float acc[TA];
        #pragma unroll
        for (int t=0;t<TA;t++) acc[t]=0.f;
        #pragma unroll 4
        for (int h = 0; h < 256; h++){
            float ev = __ldg(enc + base + (size_t)h*100 + s);
            #pragma unroll
            for (int t=0;t<TA;t++) acc[t] += cat[t*768 + 256 + h]*ev;
        }
        #pragma unroll
        for (int t=0;t<TA;t++) as_[e*TA*100 + t*100 + s] = acc[t];
    }
    __syncthreads();

    // ---- phase 2: softmax over s ----
    const int wid = tid >> 5, lane = tid & 31;
    for (int row = wid; row < 2*TA; row += 8){
        float x0 = as_[row*100 + lane];
        float x1 = as_[row*100 + lane + 32];
        float x2 = as_[row*100 + lane + 64];
        float x3 = (lane < 4) ? as_[row*100 + lane + 96] : -INFINITY;
        float m = fmaxf(fmaxf(x0,x1), fmaxf(x2,x3));
        #pragma unroll
        for (int o=16;o;o>>=1) m = fmaxf(m, __shfl_xor_sync(0xffffffff,m,o));
        float e0 = fexp(x0-m), e1 = fexp(x1-m), e2 = fexp(x2-m);
        float e3 = (lane < 4) ? fexp(x3-m) : 0.f;
        float s = e0+e1+e2+e3;
        #pragma unroll
        for (int o=16;o;o>>=1) s += __shfl_xor_sync(0xffffffff,s,o);
        float inv = 1.f/s;
        as_[row*100 + lane     ] = e0*inv;
        as_[row*100 + lane + 32] = e1*inv;
        as_[row*100 + lane + 64] = e2*inv;
        if (lane < 4) as_[row*100 + lane + 96] = e3*inv;
    }
    __syncthreads();

    // ---- phase 3: ctx -> cat[.,0:256], ast_ctx -> cat[.,512:768] ----
    const int h = tid;
    #pragma unroll
    for (int e = 0; e < 2; e++){
        const float* enc = e ? ast : tok;
        float acc[TA];
        #pragma unroll
        for (int t=0;t<TA;t++) acc[t]=0.f;
        #pragma unroll 4
        for (int s = 0; s < 100; s++){
            float ev = __ldg(enc + base + (size_t)s*256 + h);
            #pragma unroll
            for (int t=0;t<TA;t++) acc[t] += as_[e*TA*100 + t*100 + s]*ev;
        }
        #pragma unroll
        for (int t=0;t<TA;t++)
            cat[t*768 + e*512 + h] = acc[t];
    }
    __syncthreads();

    // ---- phase 4: hid = relu(cat @ W1^T + b1), W1 streamed ----
    float acc[TA];
    #pragma unroll
    for (int r=0;r<TA;r++) acc[r]=0.f;

    for (int c = 0; c < HCH; c++){
        CP_WAIT1();
        __syncthreads();
        const int st = c % 3;

        if (c + 2 < HCH){
            const uint32_t so = (uint32_t)((c+2) % 3)*8192;
            CP16(w1dst[0] + so, w1src[0] + (c+2)*2048);
            CP16(w1dst[1] + so, w1src[1] + (c+2)*2048);
        }
        CP_COMMIT();

        #pragma unroll
        for (int ii = 0; ii < 8; ii++){
            float w = w1s[st][ii*256 + tid];
            const int i = c*8 + ii;
            #pragma unroll
            for (int r=0;r<TA;r++)
                acc[r] = fmaf(cat[r*768 + i], w, acc[r]);
        }
    }

    const float bb = b1[tid];
    __syncthreads();
    #pragma unroll
    for (int r=0;r<TA;r++)
        as_[r*256 + tid] = fmaxf(acc[r] + bb, 0.f);   // reuse as_ (5*256 <= 1000)
    __syncthreads();

    // ---- phase 5: fp16 hi/lo split -> g_Ah/g_Al (5 rows x 128 pairs) ----
    for (int idx = tid; idx < TA*128; idx += 256){
        int r = idx / 128, p = idx % 128;
        float f0 = as_[r*256 + 2*p];
        float f1 = as_[r*256 + 2*p + 1];
        uint32_t hi, lo;
        split2(f0, f1, hi, lo);
        size_t gi = (size_t)(b*TT + t0 + r)*128 + p;
        g_Ah[gi] = hi;
        g_Al[gi] = lo;
    }
}

// ---------------------------------------------------------
// K4: fp16x2-split mma.sync GEMM, 3-stage cp.async, 2 CTAs/SM,
//     m-fast grid, fused softmax partials, fp16 logit store
// ---------------------------------------------------------
#define KCH 16
#define ROWSTR 48
#define TILE_B   6144
#define STAGE_B  24576
#define OFF_BIAS (3*STAGE_B)
#define OFF_SM   (OFF_BIAS + 512)
#define OFF_SS   (OFF_SM + 1024)
#define OFF_SI   (OFF_SS + 1024)
#define GEMM_SMEM (OFF_SI + 1024)        // 77312

__global__ __launch_bounds__(256, 2) void k_gemm_fp16(const float* __restrict__ bias)
{
    extern __shared__ char sm[];
    const uint32_t smb = smem_u32(sm);
    float* bsm = (float*)(sm + OFF_BIAS);
    float* s_m = (float*)(sm + OFF_SM);
    float* s_s = (float*)(sm + OFF_SS);
    int*   s_i = (int*)  (sm + OFF_SI);

    const int tid  = threadIdx.x;
    const int lane = tid & 31;
    const int warp = tid >> 5;
    const int wm   = warp & 3;
    const int wn   = warp >> 2;
    const int tig  = lane & 3;
    const int g    = lane >> 2;
    const int m0   = blockIdx.x * 128;
    const int n0   = blockIdx.y * 128;

    if (tid < 128) bsm[tid] = (n0 + tid < VV) ? bias[n0 + tid] : 0.f;

    const int lr = tid >> 1;
    const int lh = tid & 1;
    const bool bval = (n0 + lr) < VV;
    const uint32_t* srcAh = g_Ah + (size_t)(m0 + lr)*128 + lh*4;
    const uint32_t* srcAl = g_Al + (size_t)(m0 + lr)*128 + lh*4;
    const uint32_t* srcBh = g_W2h + (bval ? (size_t)(n0 + lr)*128 : 0) + lh*4;
    const uint32_t* srcBl = g_W2l + (bval ? (size_t)(n0 + lr)*128 : 0) + lh*4;
    const uint32_t dA = smb + lr*ROWSTR + lh*16;
    const uint32_t dB = dA + 2*TILE_B;

    const uint32_t aAddr0 = smb + (wm*32 + (lane & 15))*ROWSTR + ((lane >> 4) << 4);
    uint32_t bAddr[4];
    {
        const uint32_t brow = wn*64 + ((lane >> 4) << 3) + (lane & 7);
        const uint32_t boff = ((lane >> 3) & 1) << 4;
        #pragma unroll
        for (int j = 0; j < 4; j++)
            bAddr[j] = smb + 2*TILE_B + (brow + j*16)*ROWSTR + boff;
    }

    float acc[2][8][4];
    #pragma unroll
    for (int i=0;i<2;i++)
        #pragma unroll
        for (int j=0;j<8;j++)
            #pragma unroll
            for (int t=0;t<4;t++) acc[i][j][t]=0.f;

    #pragma unroll
    for (int c = 0; c < 2; c++){
        const uint32_t so = c*STAGE_B;
        CP16(dA + so,          srcAh + c*8);
        CP16(dA + so + TILE_B, srcAl + c*8);
        CP16(dB + so,          srcBh + c*8);
        CP16(dB + so + TILE_B, srcBl + c*8);
        CP_COMMIT();
    }

    for (int c = 0; c < KCH; c++){
        const int st = c % 3;
        const uint32_t so = st*STAGE_B;
        CP_WAIT1();
        __syncthreads();

        uint32_t ah[2][4], al[2][4], bh[4][4], bl[4][4];
        #pragma unroll
        for (int i = 0; i < 2; i++){
            LDSM4(ah[i], aAddr0 + so + i*16*ROWSTR);
            LDSM4(al[i], aAddr0 + so + i*16*ROWSTR + TILE_B);
        }
        #pragma unroll
        for (int j = 0; j < 4; j++){
            LDSM4(bh[j], bAddr[j] + so);
            LDSM4(bl[j], bAddr[j] + so + TILE_B);
        }

        if (c + 2 < KCH){
            const uint32_t so2 = (uint32_t)((c+2) % 3)*STAGE_B;
            CP16(dA + so2,          srcAh + (c+2)*8);
            CP16(dA + so2 + TILE_B, srcAl + (c+2)*8);
            CP16(dB + so2,          srcBh + (c+2)*8);
            CP16(dB + so2 + TILE_B, srcBl + (c+2)*8);
        }
        CP_COMMIT();

        #pragma unroll
        for (int i = 0; i < 2; i++)
            #pragma unroll
            for (int j = 0; j < 8; j++)
                MMA16(acc[i][j], ah[i], &bh[j>>1][(j&1)*2]);
        #pragma unroll
        for (int i = 0; i < 2; i++)
            #pragma unroll
            for (int j = 0; j < 8; j++)
                MMA16(acc[i][j], ah[i], &bl[j>>1][(j&1)*2]);
        #pragma unroll
        for (int i = 0; i < 2; i++)
            #pragma unroll
            for (int j = 0; j < 8; j++)
                MMA16(acc[i][j], al[i], &bh[j>>1][(j&1)*2]);
    }
    __syncthreads();

    // ---- epilogue: bias + relu + partial stats (fp32) + fp16 store ----
    #pragma unroll
    for (int i=0;i<2;i++){
        #pragma unroll
        for (int h=0;h<2;h++){
            const int r = wm*32 + i*16 + h*8 + g;
            float vv[16];
            float mx = -1e30f; int ai = 0x7fffffff;
            #pragma unroll
            for (int j=0;j<8;j++){
                #pragma unroll
                for (int t=0;t<2;t++){
                    int col = wn*64 + j*8 + 2*tig + t;
                    bool ok = (n0 + col) < VV;
                    float v = ok ? fmaxf(acc[i][j][h*2+t] + bsm[col], 0.f) : -1e30f;
                    vv[j*2+t] = v;
                    if (v > mx){ mx = v; ai = n0 + col; }
                }
            }
            #pragma unroll
            for (int msk=1; msk<=2; msk<<=1){
                float m2 = __shfl_xor_sync(0xffffffff, mx, msk);
                int   i2 = __shfl_xor_sync(0xffffffff, ai, msk);
                if (m2 > mx || (m2 == mx && i2 < ai)){ mx = m2; ai = i2; }
            }
            float s = 0.f;
            #pragma unroll
            for (int u=0;u<16;u++)
                s += (vv[u] > -1e29f) ? fexp(vv[u] - mx) : 0.f;
            #pragma unroll
            for (int msk=1; msk<=2; msk<<=1)
                s += __shfl_xor_sync(0xffffffff, s, msk);
            if (tig == 0){
                s_m[wn*128 + r] = mx; s_s[wn*128 + r] = s; s_i[wn*128 + r] = ai;
            }
            uint32_t* crow = g_C16 + (size_t)(m0 + r)*(VV/2) + n0/2;
            #pragma unroll
            for (int j=0;j<8;j++){
                int col = wn*64 + j*8 + 2*tig;
                if (n0 + col + 1 < VV){
                    half2 hv = __floats2half2_rn(vv[j*2], vv[j*2+1]);
                    crow[col/2] = *(uint32_t*)&hv;
                }
            }
        }
    }
    __syncthreads();
    if (tid < 128){
        float m1 = s_m[tid], m2 = s_m[128 + tid];
        float s1 = s_s[tid], s2 = s_s[128 + tid];
        int   i1 = s_i[tid], i2 = s_i[128 + tid];
        float mm = fmaxf(m1, m2);
        float ss = s1*fexps(m1-mm) + s2*fexps(m2-mm);
        int   ii = (m2 > m1 || (m2 == m1 && i2 < i1)) ? i2 : i1;
        int row = m0 + tid;
        g_pm[(size_t)row*NTILE + blockIdx.y] = mm;
        g_ps[(size_t)row*NTILE + blockIdx.y] = ss;
        g_pi[(size_t)row*NTILE + blockIdx.y] = ii;
    }
}

// ---------------------------------------------------------
// K5: fused stats + normalization. One block per row.
// ---------------------------------------------------------
__global__ __launch_bounds__(256) void k_norm(float* __restrict__ logp,
                                              float* __restrict__ seq)
{
    __shared__ float sm[256], ss[256];
    __shared__ int   si[256];
    __shared__ float sh_off;
    const int row = blockIdx.x;
    const int tid = threadIdx.x;

    float m = -1e30f, s = 0.f;
    int i = 0x7fffffff;
    for (int t = tid; t < NTILE; t += 256){
        float m2 = g_pm[(size_t)row*NTILE + t];
        float s2 = g_ps[(size_t)row*NTILE + t];
        int   i2 = g_pi[(size_t)row*NTILE + t];
        float mm = fmaxf(m, m2);
        s = s*fexps(m - mm) + s2*fexps(m2 - mm);
        i = (m2 > m || (m2 == m && i2 < i)) ? i2 : i;
        m = mm;
    }
    sm[tid]=m; ss[tid]=s; si[tid]=i;
    __syncthreads();
    for (int off = 128; off; off >>= 1){
        if (tid < off){
            float m1=sm[tid],     s1=ss[tid];     int i1=si[tid];
            float m2=sm[tid+off], s2=ss[tid+off]; int i2=si[tid+off];
            float mm = fmaxf(m1,m2);
            float sn = s1*fexps(m1-mm) + s2*fexps(m2-mm);
            int ia = (m2 > m1 || (m2 == m1 && i2 < i1)) ? i2 : i1;
            sm[tid]=mm; ss[tid]=sn; si[tid]=ia;
        }
        __syncthreads();
    }
    if (tid == 0){
        sh_off = sm[0] + logf(ss[0]);
        if (seq) seq[row] = (float)si[0];
    }
    __syncthreads();
    const float off = sh_off;

    const uint4* src = (const uint4*)(g_C16 + (size_t)row*(VV/2));
    float4* dst = (float4*)(logp + (size_t)row*VV);
    for (int idx = tid; idx < VV/8; idx += 256){
        uint4 v = __ldcs(src + idx);
        float2 a = __half22float2(*(half2*)&v.x);
        float2 b = __half22float2(*(half2*)&v.y);
        float2 c = __half22float2(*(half2*)&v.z);
        float2 d = __half22float2(*(half2*)&v.w);
        float4 o0 = make_float4(a.x - off, a.y - off, b.x - off, b.y - off);
        float4 o1 = make_float4(c.x - off, c.y - off, d.x - off, d.y - off);
        __stcs(dst + idx*2,     o0);
        __stcs(dst + idx*2 + 1, o1);
    }
}

// ---------------------------------------------------------
extern "C" void kernel_launch(void* const* d_in, const int* in_sizes, int n_in,
                              void* d_out, int out_size)
{
    const int*   ci   = (const int*)  d_in[1];
    const float* tok  = (const float*)d_in[2];
    const float* hc   = (const float*)d_in[3];
    const float* astp = (const float*)d_in[4];
    const float* wemb = (const float*)d_in[5];
    const float* Wih  = (const float*)d_in[6];
    const float* Whh  = (const float*)d_in[7];
    const float* bih  = (const float*)d_in[8];
    const float* bhh  = (const float*)d_in[9];
    const float* W1   = (const float*)d_in[10];
    const float* b1   = (const float*)d_in[11];
    const float* W2   = (const float*)d_in[12];
    const float* b2   = (const float*)d_in[13];

    float* out = (float*)d_out;
    long long off = (long long)out_size - (long long)ROWS*VV;
    if (off < 0) off = 0;
    float* logp = out + off;
    float* seq  = (off >= ROWS) ? out : nullptr;

    cudaFuncSetAttribute(k_gemm_fp16, cudaFuncAttributeMaxDynamicSharedMemorySize, GEMM_SMEM);

    k_prep<<<(3*NW + 255)/256, 256>>>(Wih, Whh, W1);
    k_dec<<<dim3(3, BB, 2), 256>>>(ci, hc, wemb, bih, bhh, W2);
    k_attn_hid<<<dim3(6, BB, 2), 256>>>(tok, astp, b1, W2);
    k_gemm_fp16<<<dim3(15, NTILE), 256, GEMM_SMEM>>>(b2);
    k_norm<<<ROWS, 256>>>(logp, seq);
}

// round 16
// speedup vs baseline: 1.0195x; 1.0195x over previous
#include <cuda_runtime.h>
#include <cuda_fp16.h>
#include <math.h>
#include <stdint.h>

// Problem constants
#define BB   64
#define TT   30
#define SS   100
#define HH   256
#define ROWS (BB*TT)      // 1920
#define VV   50000
#define NTILE 391         // ceil(50000/128)

// -------- device scratch --------
__device__ float    g_cat [ROWS*768];
__device__ uint32_t g_Ah  [ROWS*128];
__device__ uint32_t g_Al  [ROWS*128];
__device__ uint32_t g_W2h [(size_t)VV*128];
__device__ uint32_t g_W2l [(size_t)VV*128];
__device__ uint32_t g_C16 [(size_t)ROWS*(VV/2)];   // logits as half2 (192MB)
__device__ float    g_Wiht[HH*768];
__device__ float    g_Whht[HH*768];
__device__ float    g_W1t [768*HH];
__device__ float    g_pm  [(size_t)ROWS*NTILE];
__device__ float    g_ps  [(size_t)ROWS*NTILE];
__device__ int      g_pi  [(size_t)ROWS*NTILE];

__device__ __forceinline__ float sigm(float x){ return 1.f/(1.f+expf(-x)); }

// fast e^x (poly exp2, ~3e-8 rel)
__device__ __forceinline__ float fexp(float x){
    float y = x * 1.44269504088896341f;
    float z = y + 12582912.0f;
    int   n = __float_as_int(z);
    float f = y - (z - 12582912.0f);
    float p =              1.53386992e-4f;
    p = fmaf(p, f,         1.33335581e-3f);
    p = fmaf(p, f,         9.61812911e-3f);
    p = fmaf(p, f,         5.55041087e-2f);
    p = fmaf(p, f,         2.40226507e-1f);
    p = fmaf(p, f,         6.93147181e-1f);
    p = fmaf(p, f,         1.0f);
    return __int_as_float(__float_as_int(p) + (n << 23));
}
__device__ __forceinline__ float fexps(float x){
    return (x < -80.f) ? 0.f : fexp(x);
}

__device__ __forceinline__ void split2(float f0, float f1, uint32_t& hi, uint32_t& lo){
    half h0 = __float2half_rn(f0);
    half h1 = __float2half_rn(f1);
    half l0 = __float2half_rn(f0 - __half2float(h0));
    half l1 = __float2half_rn(f1 - __half2float(h1));
    half2 H = __halves2half2(h0, h1);
    half2 L = __halves2half2(l0, l1);
    hi = *(uint32_t*)&H;
    lo = *(uint32_t*)&L;
}

__device__ __forceinline__ uint32_t smem_u32(const void* p){
    uint32_t a;
    asm("{ .reg .u64 t; cvta.to.shared.u64 t, %1; cvt.u32.u64 %0, t; }" : "=r"(a) : "l"(p));
    return a;
}

// W2 split work distributed into small kernels' tail blocks.
#define QTOT 3200000L
__device__ void w2split_quads(const float* __restrict__ W2,
                              long q0, long q1, int bid, int nb)
{
    const long stride = (long)nb * 256;
    for (long q = q0 + (long)bid*256 + threadIdx.x; q < q1; q += stride){
        float4 f = ((const float4*)W2)[q];
        uint32_t h0, l0, h1, l1;
        split2(f.x, f.y, h0, l0);
        split2(f.z, f.w, h1, l1);
        *(uint2*)&g_W2h[q*2] = make_uint2(h0, h1);
        *(uint2*)&g_W2l[q*2] = make_uint2(l0, l1);
    }
}
#define QD0 0L
#define QD1 753000L
#define QA1 2259000L

#define MMA16(d, a, b) asm volatile( \
 "mma.sync.aligned.m16n8k16.row.col.f32.f16.f16.f32 " \
 "{%0,%1,%2,%3}, {%4,%5,%6,%7}, {%8,%9}, {%0,%1,%2,%3};" \
 : "+f"((d)[0]), "+f"((d)[1]), "+f"((d)[2]), "+f"((d)[3]) \
 : "r"((a)[0]), "r"((a)[1]), "r"((a)[2]), "r"((a)[3]), "r"((b)[0]), "r"((b)[1]))

#define LDSM4(r, addr) asm volatile( \
 "ldmatrix.sync.aligned.m8n8.x4.shared.b16 {%0,%1,%2,%3}, [%4];" \
 : "=r"((r)[0]), "=r"((r)[1]), "=r"((r)[2]), "=r"((r)[3]) : "r"(addr))

// .cg: bypass L1 (staged data is never re-read through L1; frees
// L1tex bandwidth for the LDSM fragment stream, the observed bottleneck)
#define CP16(dst, src) asm volatile( \
 "cp.async.cg.shared.global [%0], [%1], 16;" :: "r"(dst), "l"(src) : "memory")
#define CP_COMMIT() asm volatile("cp.async.commit_group;" ::: "memory")
#define CP_WAIT1()  asm volatile("cp.async.wait_group 1;" ::: "memory")

// ---------------------------------------------------------
// K0: weight transposes only
// ---------------------------------------------------------
#define NW (768*256)
__global__ void k_prep(const float* __restrict__ Wih,
                       const float* __restrict__ Whh,
                       const float* __restrict__ W1)
{
    int idx = blockIdx.x*blockDim.x + threadIdx.x;
    if (idx < NW){
        int k = idx/768, c = idx%768;
        g_Wiht[idx] = Wih[c*256 + k];
    } else if (idx < 2*NW){
        int j = idx - NW; int k = j/768, c = j%768;
        g_Whht[j] = Whh[c*256 + k];
    } else if (idx < 3*NW){
        int j = idx - 2*NW; int i = j/256, o = j%256;
        g_W1t[j] = W1[o*768 + i];
    }
}

// ---------------------------------------------------------
// K1: GRU decode   grid (3, 64, 2); z=1 blocks do W2 split
// ---------------------------------------------------------
__global__ __launch_bounds__(256) void k_dec(const int*   __restrict__ ci,
                                             const float* __restrict__ hc,
                                             const float* __restrict__ wemb,
                                             const float* __restrict__ bih,
                                             const float* __restrict__ bhh,
                                             const float* __restrict__ W2)
{
    if (blockIdx.z == 1){
        w2split_quads(W2, QD0, QD1, blockIdx.y*3 + blockIdx.x, 3*BB);
        return;
    }
    __shared__ float h0s[256];
    __shared__ float embs[10*256];
    const int b  = blockIdx.y;
    const int tg = blockIdx.x;
    const int j  = threadIdx.x;

    h0s[j] = hc[b*256 + j];
    for (int i = j; i < 10*256; i += 256){
        int r = i >> 8, k = i & 255;
        int tok = ci[b*TT + tg*10 + r];
        embs[i] = wemb[(size_t)tok*256 + k];
    }
    __syncthreads();

    float ghr = bhh[j], ghz = bhh[256+j], ghn = bhh[512+j];
    for (int k = 0; k < 256; k++){
        float hv = h0s[k];
        ghr += g_Whht[k*768 +       j]*hv;
        ghz += g_Whht[k*768 + 256 + j]*hv;
        ghn += g_Whht[k*768 + 512 + j]*hv;
    }

    float aR[10], aZ[10], aN[10];
    #pragma unroll
    for (int r=0;r<10;r++){ aR[r]=0.f; aZ[r]=0.f; aN[r]=0.f; }
    for (int k = 0; k < 256; k++){
        float wr = g_Wiht[k*768 +       j];
        float wz = g_Wiht[k*768 + 256 + j];
        float wn = g_Wiht[k*768 + 512 + j];
        #pragma unroll
        for (int r=0;r<10;r++){
            float e = embs[r*256 + k];
            aR[r] += wr*e; aZ[r] += wz*e; aN[r] += wn*e;
        }
    }
    const float bR = bih[j], bZ = bih[256+j], bN = bih[512+j];
    const float h0v = h0s[j];
    #pragma unroll
    for (int r=0;r<10;r++){
        float rr  = sigm(aR[r] + bR + ghr);
        float zz  = sigm(aZ[r] + bZ + ghz);
        float nn  = tanhf(aN[r] + bN + rr*ghn);
        float dec = (1.f - zz)*nn + zz*h0v;
        int row = b*TT + tg*10 + r;
        g_cat[(size_t)row*768 + 256 + j] = dec;
    }
}

// ---------------------------------------------------------
// K2: dual attention (raw-reshape keys!)  grid (6, 64, 2)
// ---------------------------------------------------------
#define TA 5
__global__ __launch_bounds__(256) void k_attn(const float* __restrict__ tok,
                                              const float* __restrict__ ast,
                                              const float* __restrict__ W2)
{
    if (blockIdx.z == 1){
        w2split_quads(W2, QD1, QA1, blockIdx.y*6 + blockIdx.x, 6*BB);
        return;
    }
    __shared__ float decs[TA*256];
    __shared__ float as_ [2*TA*100];
    const int b  = blockIdx.y;
    const int tg = blockIdx.x;
    const int tid = threadIdx.x;
    const int t0 = tg*TA;

    for (int i = tid; i < TA*256; i += 256){
        int t = i >> 8, h = i & 255;
        decs[i] = g_cat[(size_t)(b*TT + t0 + t)*768 + 256 + h];
    }
    __syncthreads();

    const size_t base = (size_t)b * (SS*HH);

    if (tid < 200){
        const int e = tid / 100;
        const int s = tid % 100;
        const float* enc = e ? ast : tok;
        float acc[TA];
        #pragma unroll
        for (int t=0;t<TA;t++) acc[t]=0.f;
        #pragma unroll 4
        for (int h = 0; h < 256; h++){
            float ev = __ldg(enc + base + (size_t)h*100 + s);
            #pragma unroll
            for (int t=0;t<TA;t++) acc[t] += decs[t*256 + h]*ev;
        }
        #pragma unroll
        for (int t=0;t<TA;t++) as_[e*TA*100 + t*100 + s] = acc[t];
    }
    __syncthreads();

    const int wid = tid >> 5, lane = tid & 31;
    for (int row = wid; row < 2*TA; row += 8){
        float x0 = as_[row*100 + lane];
        float x1 = as_[row*100 + lane + 32];
        float x2 = as_[row*100 + lane + 64];
        float x3 = (lane < 4) ? as_[row*100 + lane + 96] : -INFINITY;
        float m = fmaxf(fmaxf(x0,x1), fmaxf(x2,x3));
        #pragma unroll
        for (int o=16;o;o>>=1) m = fmaxf(m, __shfl_xor_sync(0xffffffff,m,o));
        float e0 = fexp(x0-m), e1 = fexp(x1-m), e2 = fexp(x2-m);
        float e3 = (lane < 4) ? fexp(x3-m) : 0.f;
        float s = e0+e1+e2+e3;
        #pragma unroll
        for (int o=16;o;o>>=1) s += __shfl_xor_sync(0xffffffff,s,o);
        float inv = 1.f/s;
        as_[row*100 + lane     ] = e0*inv;
        as_[row*100 + lane + 32] = e1*inv;
        as_[row*100 + lane + 64] = e2*inv;
        if (lane < 4) as_[row*100 + lane + 96] = e3*inv;
    }
    __syncthreads();

    const int h = tid;
    #pragma unroll
    for (int e = 0; e < 2; e++){
        const float* enc = e ? ast : tok;
        float acc[TA];
        #pragma unroll
        for (int t=0;t<TA;t++) acc[t]=0.f;
        #pragma unroll 4
        for (int s = 0; s < 100; s++){
            float ev = __ldg(enc + base + (size_t)s*256 + h);
            #pragma unroll
            for (int t=0;t<TA;t++) acc[t] += as_[e*TA*100 + t*100 + s]*ev;
        }
        #pragma unroll
        for (int t=0;t<TA;t++)
            g_cat[(size_t)(b*TT + t0 + t)*768 + e*512 + h] = acc[t];
    }
}

// ---------------------------------------------------------
// K3: hid = relu(cat @ W1^T + b1) -> fp16 hi/lo splits,
//     W1t staged via 3-stage cp.async ring.  grid (240,1,2)
// ---------------------------------------------------------
#define HCH 96
__global__ __launch_bounds__(256) void k_hid(const float* __restrict__ b1,
                                             const float* __restrict__ W2)
{
    if (blockIdx.z == 1){
        w2split_quads(W2, QA1, QTOT, blockIdx.x, 240);
        return;
    }
    __shared__ float cats[8*768];
    __shared__ float w1s[3][8*256];
    const int rb = blockIdx.x;
    const int o  = threadIdx.x;

    uint32_t w1dst[2];
    const float* w1src[2];
    #pragma unroll
    for (int it = 0; it < 2; it++){
        int seg = it*256 + o;
        int row = seg >> 6;
        int col4 = (seg & 63) * 4;
        w1dst[it] = smem_u32(&w1s[0][row*256 + col4]);
        w1src[it] = g_W1t + row*256 + col4;
    }

    #pragma unroll
    for (int c = 0; c < 2; c++){
        CP16(w1dst[0] + c*8192, w1src[0] + c*2048);
        CP16(w1dst[1] + c*8192, w1src[1] + c*2048);
        CP_COMMIT();
    }

    for (int i = o; i < 8*768; i += 256)
        cats[i] = g_cat[(size_t)rb*8*768 + i];
    __syncthreads();

    float acc[8];
    #pragma unroll
    for (int r=0;r<8;r++) acc[r]=0.f;

    for (int c = 0; c < HCH; c++){
        CP_WAIT1();
        __syncthreads();
        const int st = c % 3;

        if (c + 2 < HCH){
            const uint32_t so = (uint32_t)((c+2) % 3)*8192;
            CP16(w1dst[0] + so, w1src[0] + (c+2)*2048);
            CP16(w1dst[1] + so, w1src[1] + (c+2)*2048);
        }
        CP_COMMIT();

        #pragma unroll
        for (int ii = 0; ii < 8; ii++){
            float w = w1s[st][ii*256 + o];
            const int i = c*8 + ii;
            #pragma unroll
            for (int r=0;r<8;r++)
                acc[r] = fmaf(cats[r*768 + i], w, acc[r]);
        }
    }

    const float bb = b1[o];
    __syncthreads();
    #pragma unroll
    for (int r=0;r<8;r++)
        cats[r*256 + o] = fmaxf(acc[r] + bb, 0.f);
    __syncthreads();

    for (int idx = o; idx < 1024; idx += 256){
        int r = idx >> 7, p = idx & 127;
        float f0 = cats[r*256 + 2*p];
        float f1 = cats[r*256 + 2*p + 1];
        uint32_t hi, lo;
        split2(f0, f1, hi, lo);
        size_t gi = (size_t)(rb*8 + r)*128 + p;
        g_Ah[gi] = hi;
        g_Al[gi] = lo;
    }
}

// ---------------------------------------------------------
// K4: fp16x2-split mma.sync GEMM, 3-stage cp.async(.cg), 2 CTAs/SM,
//     m-fast grid, fused softmax partials, fp16 logit store
// ---------------------------------------------------------
#define KCH 16
#define ROWSTR 48
#define TILE_B   6144
#define STAGE_B  24576
#define OFF_BIAS (3*STAGE_B)
#define OFF_SM   (OFF_BIAS + 512)
#define OFF_SS   (OFF_SM + 1024)
#define OFF_SI   (OFF_SS + 1024)
#define GEMM_SMEM (OFF_SI + 1024)        // 77312

__global__ __launch_bounds__(256, 2) void k_gemm_fp16(const float* __restrict__ bias)
{
    extern __shared__ char sm[];
    const uint32_t smb = smem_u32(sm);
    float* bsm = (float*)(sm + OFF_BIAS);
    float* s_m = (float*)(sm + OFF_SM);
    float* s_s = (float*)(sm + OFF_SS);
    int*   s_i = (int*)  (sm + OFF_SI);

    const int tid  = threadIdx.x;
    const int lane = tid & 31;
    const int warp = tid >> 5;
    const int wm   = warp & 3;
    const int wn   = warp >> 2;
    const int tig  = lane & 3;
    const int g    = lane >> 2;
    const int m0   = blockIdx.x * 128;
    const int n0   = blockIdx.y * 128;

    if (tid < 128) bsm[tid] = (n0 + tid < VV) ? bias[n0 + tid] : 0.f;

    const int lr = tid >> 1;
    const int lh = tid & 1;
    const bool bval = (n0 + lr) < VV;
    const uint32_t* srcAh = g_Ah + (size_t)(m0 + lr)*128 + lh*4;
    const uint32_t* srcAl = g_Al + (size_t)(m0 + lr)*128 + lh*4;
    const uint32_t* srcBh = g_W2h + (bval ? (size_t)(n0 + lr)*128 : 0) + lh*4;
    const uint32_t* srcBl = g_W2l + (bval ? (size_t)(n0 + lr)*128 : 0) + lh*4;
    const uint32_t dA = smb + lr*ROWSTR + lh*16;
    const uint32_t dB = dA + 2*TILE_B;

    const uint32_t aAddr0 = smb + (wm*32 + (lane & 15))*ROWSTR + ((lane >> 4) << 4);
    uint32_t bAddr[4];
    {
        const uint32_t brow = wn*64 + ((lane >> 4) << 3) + (lane & 7);
        const uint32_t boff = ((lane >> 3) & 1) << 4;
        #pragma unroll
        for (int j = 0; j < 4; j++)
            bAddr[j] = smb + 2*TILE_B + (brow + j*16)*ROWSTR + boff;
    }

    float acc[2][8][4];
    #pragma unroll
    for (int i=0;i<2;i++)
        #pragma unroll
        for (int j=0;j<8;j++)
            #pragma unroll
            for (int t=0;t<4;t++) acc[i][j][t]=0.f;

    #pragma unroll
    for (int c = 0; c < 2; c++){
        const uint32_t so = c*STAGE_B;
        CP16(dA + so,          srcAh + c*8);
        CP16(dA + so + TILE_B, srcAl + c*8);
        CP16(dB + so,          srcBh + c*8);
        CP16(dB + so + TILE_B, srcBl + c*8);
        CP_COMMIT();
    }

    for (int c = 0; c < KCH; c++){
        const int st = c % 3;
        const uint32_t so = st*STAGE_B;
        CP_WAIT1();
        __syncthreads();

        uint32_t ah[2][4], al[2][4], bh[4][4], bl[4][4];
        #pragma unroll
        for (int i = 0; i < 2; i++){
            LDSM4(ah[i], aAddr0 + so + i*16*ROWSTR);
            LDSM4(al[i], aAddr0 + so + i*16*ROWSTR + TILE_B);
        }
        #pragma unroll
        for (int j = 0; j < 4; j++){
            LDSM4(bh[j], bAddr[j] + so);
            LDSM4(bl[j], bAddr[j] + so + TILE_B);
        }

        if (c + 2 < KCH){
            const uint32_t so2 = (uint32_t)((c+2) % 3)*STAGE_B;
            CP16(dA + so2,          srcAh + (c+2)*8);
            CP16(dA + so2 + TILE_B, srcAl + (c+2)*8);
            CP16(dB + so2,          srcBh + (c+2)*8);
            CP16(dB + so2 + TILE_B, srcBl + (c+2)*8);
        }
        CP_COMMIT();

        #pragma unroll
        for (int i = 0; i < 2; i++)
            #pragma unroll
            for (int j = 0; j < 8; j++)
                MMA16(acc[i][j], ah[i], &bh[j>>1][(j&1)*2]);
        #pragma unroll
        for (int i = 0; i < 2; i++)
            #pragma unroll
            for (int j = 0; j < 8; j++)
                MMA16(acc[i][j], ah[i], &bl[j>>1][(j&1)*2]);
        #pragma unroll
        for (int i = 0; i < 2; i++)
            #pragma unroll
            for (int j = 0; j < 8; j++)
                MMA16(acc[i][j], al[i], &bh[j>>1][(j&1)*2]);
    }
    __syncthreads();

    // ---- epilogue: bias + relu + partial stats (fp32) + fp16 store ----
    #pragma unroll
    for (int i=0;i<2;i++){
        #pragma unroll
        for (int h=0;h<2;h++){
            const int r = wm*32 + i*16 + h*8 + g;
            float vv[16];
            float mx = -1e30f; int ai = 0x7fffffff;
            #pragma unroll
            for (int j=0;j<8;j++){
                #pragma unroll
                for (int t=0;t<2;t++){
                    int col = wn*64 + j*8 + 2*tig + t;
                    bool ok = (n0 + col) < VV;
                    float v = ok ? fmaxf(acc[i][j][h*2+t] + bsm[col], 0.f) : -1e30f;
                    vv[j*2+t] = v;
                    if (v > mx){ mx = v; ai = n0 + col; }
                }
            }
            #pragma unroll
            for (int msk=1; msk<=2; msk<<=1){
                float m2 = __shfl_xor_sync(0xffffffff, mx, msk);
                int   i2 = __shfl_xor_sync(0xffffffff, ai, msk);
                if (m2 > mx || (m2 == mx && i2 < ai)){ mx = m2; ai = i2; }
            }
            float s = 0.f;
            #pragma unroll
            for (int u=0;u<16;u++)
                s += (vv[u] > -1e29f) ? fexp(vv[u] - mx) : 0.f;
            #pragma unroll
            for (int msk=1; msk<=2; msk<<=1)
                s += __shfl_xor_sync(0xffffffff, s, msk);
            if (tig == 0){
                s_m[wn*128 + r] = mx; s_s[wn*128 + r] = s; s_i[wn*128 + r] = ai;
            }
            uint32_t* crow = g_C16 + (size_t)(m0 + r)*(VV/2) + n0/2;
            #pragma unroll
            for (int j=0;j<8;j++){
                int col = wn*64 + j*8 + 2*tig;
                if (n0 + col + 1 < VV){
                    half2 hv = __floats2half2_rn(vv[j*2], vv[j*2+1]);
                    crow[col/2] = *(uint32_t*)&hv;
                }
            }
        }
    }
    __syncthreads();
    if (tid < 128){
        float m1 = s_m[tid], m2 = s_m[128 + tid];
        float s1 = s_s[tid], s2 = s_s[128 + tid];
        int   i1 = s_i[tid], i2 = s_i[128 + tid];
        float mm = fmaxf(m1, m2);
        float ss = s1*fexps(m1-mm) + s2*fexps(m2-mm);
        int   ii = (m2 > m1 || (m2 == m1 && i2 < i1)) ? i2 : i1;
        int row = m0 + tid;
        g_pm[(size_t)row*NTILE + blockIdx.y] = mm;
        g_ps[(size_t)row*NTILE + blockIdx.y] = ss;
        g_pi[(size_t)row*NTILE + blockIdx.y] = ii;
    }
}

// ---------------------------------------------------------
// K5: fused stats + normalization. One block per row.
// ---------------------------------------------------------
__global__ __launch_bounds__(256) void k_norm(float* __restrict__ logp,
                                              float* __restrict__ seq)
{
    __shared__ float sm[256], ss[256];
    __shared__ int   si[256];
    __shared__ float sh_off;
    const int row = blockIdx.x;
    const int tid = threadIdx.x;

    float m = -1e30f, s = 0.f;
    int i = 0x7fffffff;
    for (int t = tid; t < NTILE; t += 256){
        float m2 = g_pm[(size_t)row*NTILE + t];
        float s2 = g_ps[(size_t)row*NTILE + t];
        int   i2 = g_pi[(size_t)row*NTILE + t];
        float mm = fmaxf(m, m2);
        s = s*fexps(m - mm) + s2*fexps(m2 - mm);
        i = (m2 > m || (m2 == m && i2 < i)) ? i2 : i;
        m = mm;
    }
    sm[tid]=m; ss[tid]=s; si[tid]=i;
    __syncthreads();
    for (int off = 128; off; off >>= 1){
        if (tid < off){
            float m1=sm[tid],     s1=ss[tid];     int i1=si[tid];
            float m2=sm[tid+off], s2=ss[tid+off]; int i2=si[tid+off];
            float mm = fmaxf(m1,m2);
            float sn = s1*fexps(m1-mm) + s2*fexps(m2-mm);
            int ia = (m2 > m1 || (m2 == m1 && i2 < i1)) ? i2 : i1;
            sm[tid]=mm; ss[tid]=sn; si[tid]=ia;
        }
        __syncthreads();
    }
    if (tid == 0){
        sh_off = sm[0] + logf(ss[0]);
        if (seq) seq[row] = (float)si[0];
    }
    __syncthreads();
    const float off = sh_off;

    const uint4* src = (const uint4*)(g_C16 + (size_t)row*(VV/2));
    float4* dst = (float4*)(logp + (size_t)row*VV);
    for (int idx = tid; idx < VV/8; idx += 256){
        uint4 v = __ldcs(src + idx);
        float2 a = __half22float2(*(half2*)&v.x);
        float2 b = __half22float2(*(half2*)&v.y);
        float2 c = __half22float2(*(half2*)&v.z);
        float2 d = __half22float2(*(half2*)&v.w);
        float4 o0 = make_float4(a.x - off, a.y - off, b.x - off, b.y - off);
        float4 o1 = make_float4(c.x - off, c.y - off, d.x - off, d.y - off);
        __stcs(dst + idx*2,     o0);
        __stcs(dst + idx*2 + 1, o1);
    }
}

// ---------------------------------------------------------
extern "C" void kernel_launch(void* const* d_in, const int* in_sizes, int n_in,
                              void* d_out, int out_size)
{
    const int*   ci   = (const int*)  d_in[1];
    const float* tok  = (const float*)d_in[2];
    const float* hc   = (const float*)d_in[3];
    const float* astp = (const float*)d_in[4];
    const float* wemb = (const float*)d_in[5];
    const float* Wih  = (const float*)d_in[6];
    const float* Whh  = (const float*)d_in[7];
    const float* bih  = (const float*)d_in[8];
    const float* bhh  = (const float*)d_in[9];
    const float* W1   = (const float*)d_in[10];
    const float* b1   = (const float*)d_in[11];
    const float* W2   = (const float*)d_in[12];
    const float* b2   = (const float*)d_in[13];

    float* out = (float*)d_out;
    long long off = (long long)out_size - (long long)ROWS*VV;
    if (off < 0) off = 0;
    float* logp = out + off;
    float* seq  = (off >= ROWS) ? out : nullptr;

    cudaFuncSetAttribute(k_gemm_fp16, cudaFuncAttributeMaxDynamicSharedMemorySize, GEMM_SMEM);

    k_prep<<<(3*NW + 255)/256, 256>>>(Wih, Whh, W1);
    k_dec<<<dim3(3, BB, 2), 256>>>(ci, hc, wemb, bih, bhh, W2);
    k_attn<<<dim3(6, BB, 2), 256>>>(tok, astp, W2);
    k_hid<<<dim3(ROWS/8, 1, 2), 256>>>(b1, W2);
    k_gemm_fp16<<<dim3(15, NTILE), 256, GEMM_SMEM>>>(b2);
    k_norm<<<ROWS, 256>>>(logp, seq);
}

// round 17
// speedup vs baseline: 1.1388x; 1.1171x over previous
#include <cuda_runtime.h>
#include <cuda_fp16.h>
#include <math.h>
#include <stdint.h>

// Problem constants
#define BB   64
#define TT   30
#define SS   100
#define HH   256
#define ROWS (BB*TT)      // 1920
#define VV   50000
#define NTILE 391         // ceil(50000/128)

// -------- device scratch --------
__device__ float    g_cat [ROWS*768];
__device__ uint32_t g_Ah  [ROWS*128];
__device__ uint32_t g_Al  [ROWS*128];
__device__ uint32_t g_W2h [(size_t)VV*128];
__device__ uint32_t g_W2l [(size_t)VV*128];
__device__ uint32_t g_C16 [(size_t)ROWS*(VV/2)];   // logits as half2 (192MB)
__device__ float    g_Wiht[HH*768];
__device__ float    g_Whht[HH*768];
__device__ float    g_W1t [768*HH];
__device__ float    g_pm  [(size_t)ROWS*NTILE];
__device__ float    g_ps  [(size_t)ROWS*NTILE];
__device__ int      g_pi  [(size_t)ROWS*NTILE];

__device__ __forceinline__ float sigm(float x){ return 1.f/(1.f+expf(-x)); }

// fast e^x (poly exp2, ~3e-8 rel)
__device__ __forceinline__ float fexp(float x){
    float y = x * 1.44269504088896341f;
    float z = y + 12582912.0f;
    int   n = __float_as_int(z);
    float f = y - (z - 12582912.0f);
    float p =              1.53386992e-4f;
    p = fmaf(p, f,         1.33335581e-3f);
    p = fmaf(p, f,         9.61812911e-3f);
    p = fmaf(p, f,         5.55041087e-2f);
    p = fmaf(p, f,         2.40226507e-1f);
    p = fmaf(p, f,         6.93147181e-1f);
    p = fmaf(p, f,         1.0f);
    return __int_as_float(__float_as_int(p) + (n << 23));
}
__device__ __forceinline__ float fexps(float x){
    return (x < -80.f) ? 0.f : fexp(x);
}

__device__ __forceinline__ void split2(float f0, float f1, uint32_t& hi, uint32_t& lo){
    half h0 = __float2half_rn(f0);
    half h1 = __float2half_rn(f1);
    half l0 = __float2half_rn(f0 - __half2float(h0));
    half l1 = __float2half_rn(f1 - __half2float(h1));
    half2 H = __halves2half2(h0, h1);
    half2 L = __halves2half2(l0, l1);
    hi = *(uint32_t*)&H;
    lo = *(uint32_t*)&L;
}

__device__ __forceinline__ uint32_t smem_u32(const void* p){
    uint32_t a;
    asm("{ .reg .u64 t; cvta.to.shared.u64 t, %1; cvt.u32.u64 %0, t; }" : "=r"(a) : "l"(p));
    return a;
}

// W2 split work distributed into small kernels' tail blocks.
#define QTOT 3200000L
__device__ void w2split_quads(const float* __restrict__ W2,
                              long q0, long q1, int bid, int nb)
{
    const long stride = (long)nb * 256;
    for (long q = q0 + (long)bid*256 + threadIdx.x; q < q1; q += stride){
        float4 f = ((const float4*)W2)[q];
        uint32_t h0, l0, h1, l1;
        split2(f.x, f.y, h0, l0);
        split2(f.z, f.w, h1, l1);
        *(uint2*)&g_W2h[q*2] = make_uint2(h0, h1);
        *(uint2*)&g_W2l[q*2] = make_uint2(l0, l1);
    }
}
#define QD0 0L
#define QD1 753000L
#define QA1 2259000L

#define MMA16(d, a, b) asm volatile( \
 "mma.sync.aligned.m16n8k16.row.col.f32.f16.f16.f32 " \
 "{%0,%1,%2,%3}, {%4,%5,%6,%7}, {%8,%9}, {%0,%1,%2,%3};" \
 : "+f"((d)[0]), "+f"((d)[1]), "+f"((d)[2]), "+f"((d)[3]) \
 : "r"((a)[0]), "r"((a)[1]), "r"((a)[2]), "r"((a)[3]), "r"((b)[0]), "r"((b)[1]))

#define LDSM4(r, addr) asm volatile( \
 "ldmatrix.sync.aligned.m8n8.x4.shared.b16 {%0,%1,%2,%3}, [%4];" \
 : "=r"((r)[0]), "=r"((r)[1]), "=r"((r)[2]), "=r"((r)[3]) : "r"(addr))

// .cg: bypass L1 (staged data is never re-read through L1)
#define CP16(dst, src) asm volatile( \
 "cp.async.cg.shared.global [%0], [%1], 16;" :: "r"(dst), "l"(src) : "memory")
#define CP_COMMIT() asm volatile("cp.async.commit_group;" ::: "memory")
#define CP_WAIT1()  asm volatile("cp.async.wait_group 1;" ::: "memory")

// ---------------------------------------------------------
// K0: weight transposes only
// ---------------------------------------------------------
#define NW (768*256)
__global__ void k_prep(const float* __restrict__ Wih,
                       const float* __restrict__ Whh,
                       const float* __restrict__ W1)
{
    int idx = blockIdx.x*blockDim.x + threadIdx.x;
    if (idx < NW){
        int k = idx/768, c = idx%768;
        g_Wiht[idx] = Wih[c*256 + k];
    } else if (idx < 2*NW){
        int j = idx - NW; int k = j/768, c = j%768;
        g_Whht[j] = Whh[c*256 + k];
    } else if (idx < 3*NW){
        int j = idx - 2*NW; int i = j/256, o = j%256;
        g_W1t[j] = W1[o*768 + i];
    }
}

// ---------------------------------------------------------
// K1: GRU decode   grid (3, 64, 2); z=1 blocks do W2 split
// ---------------------------------------------------------
__global__ __launch_bounds__(256) void k_dec(const int*   __restrict__ ci,
                                             const float* __restrict__ hc,
                                             const float* __restrict__ wemb,
                                             const float* __restrict__ bih,
                                             const float* __restrict__ bhh,
                                             const float* __restrict__ W2)
{
    if (blockIdx.z == 1){
        w2split_quads(W2, QD0, QD1, blockIdx.y*3 + blockIdx.x, 3*BB);
        return;
    }
    __shared__ float h0s[256];
    __shared__ float embs[10*256];
    const int b  = blockIdx.y;
    const int tg = blockIdx.x;
    const int j  = threadIdx.x;

    h0s[j] = hc[b*256 + j];
    for (int i = j; i < 10*256; i += 256){
        int r = i >> 8, k = i & 255;
        int tok = ci[b*TT + tg*10 + r];
        embs[i] = wemb[(size_t)tok*256 + k];
    }
    __syncthreads();

    float ghr = bhh[j], ghz = bhh[256+j], ghn = bhh[512+j];
    for (int k = 0; k < 256; k++){
        float hv = h0s[k];
        ghr += g_Whht[k*768 +       j]*hv;
        ghz += g_Whht[k*768 + 256 + j]*hv;
        ghn += g_Whht[k*768 + 512 + j]*hv;
    }

    float aR[10], aZ[10], aN[10];
    #pragma unroll
    for (int r=0;r<10;r++){ aR[r]=0.f; aZ[r]=0.f; aN[r]=0.f; }
    for (int k = 0; k < 256; k++){
        float wr = g_Wiht[k*768 +       j];
        float wz = g_Wiht[k*768 + 256 + j];
        float wn = g_Wiht[k*768 + 512 + j];
        #pragma unroll
        for (int r=0;r<10;r++){
            float e = embs[r*256 + k];
            aR[r] += wr*e; aZ[r] += wz*e; aN[r] += wn*e;
        }
    }
    const float bR = bih[j], bZ = bih[256+j], bN = bih[512+j];
    const float h0v = h0s[j];
    #pragma unroll
    for (int r=0;r<10;r++){
        float rr  = sigm(aR[r] + bR + ghr);
        float zz  = sigm(aZ[r] + bZ + ghz);
        float nn  = tanhf(aN[r] + bN + rr*ghn);
        float dec = (1.f - zz)*nn + zz*h0v;
        int row = b*TT + tg*10 + r;
        g_cat[(size_t)row*768 + 256 + j] = dec;
    }
}

// ---------------------------------------------------------
// K2: dual attention (raw-reshape keys!)  grid (6, 64, 2)
// ---------------------------------------------------------
#define TA 5
__global__ __launch_bounds__(256) void k_attn(const float* __restrict__ tok,
                                              const float* __restrict__ ast,
                                              const float* __restrict__ W2)
{
    if (blockIdx.z == 1){
        w2split_quads(W2, QD1, QA1, blockIdx.y*6 + blockIdx.x, 6*BB);
        return;
    }
    __shared__ float decs[TA*256];
    __shared__ float as_ [2*TA*100];
    const int b  = blockIdx.y;
    const int tg = blockIdx.x;
    const int tid = threadIdx.x;
    const int t0 = tg*TA;

    for (int i = tid; i < TA*256; i += 256){
        int t = i >> 8, h = i & 255;
        decs[i] = g_cat[(size_t)(b*TT + t0 + t)*768 + 256 + h];
    }
    __syncthreads();

    const size_t base = (size_t)b * (SS*HH);

    if (tid < 200){
        const int e = tid / 100;
        const int s = tid % 100;
        const float* enc = e ? ast : tok;
        float acc[TA];
        #pragma unroll
        for (int t=0;t<TA;t++) acc[t]=0.f;
        #pragma unroll 4
        for (int h = 0; h < 256; h++){
            float ev = __ldg(enc + base + (size_t)h*100 + s);
            #pragma unroll
            for (int t=0;t<TA;t++) acc[t] += decs[t*256 + h]*ev;
        }
        #pragma unroll
        for (int t=0;t<TA;t++) as_[e*TA*100 + t*100 + s] = acc[t];
    }
    __syncthreads();

    const int wid = tid >> 5, lane = tid & 31;
    for (int row = wid; row < 2*TA; row += 8){
        float x0 = as_[row*100 + lane];
        float x1 = as_[row*100 + lane + 32];
        float x2 = as_[row*100 + lane + 64];
        float x3 = (lane < 4) ? as_[row*100 + lane + 96] : -INFINITY;
        float m = fmaxf(fmaxf(x0,x1), fmaxf(x2,x3));
        #pragma unroll
        for (int o=16;o;o>>=1) m = fmaxf(m, __shfl_xor_sync(0xffffffff,m,o));
        float e0 = fexp(x0-m), e1 = fexp(x1-m), e2 = fexp(x2-m);
        float e3 = (lane < 4) ? fexp(x3-m) : 0.f;
        float s = e0+e1+e2+e3;
        #pragma unroll
        for (int o=16;o;o>>=1) s += __shfl_xor_sync(0xffffffff,s,o);
        float inv = 1.f/s;
        as_[row*100 + lane     ] = e0*inv;
        as_[row*100 + lane + 32] = e1*inv;
        as_[row*100 + lane + 64] = e2*inv;
        if (lane < 4) as_[row*100 + lane + 96] = e3*inv;
    }
    __syncthreads();

    const int h = tid;
    #pragma unroll
    for (int e = 0; e < 2; e++){
        const float* enc = e ? ast : tok;
        float acc[TA];
        #pragma unroll
        for (int t=0;t<TA;t++) acc[t]=0.f;
        #pragma unroll 4
        for (int s = 0; s < 100; s++){
            float ev = __ldg(enc + base + (size_t)s*256 + h);
            #pragma unroll
            for (int t=0;t<TA;t++) acc[t] += as_[e*TA*100 + t*100 + s]*ev;
        }
        #pragma unroll
        for (int t=0;t<TA;t++)
            g_cat[(size_t)(b*TT + t0 + t)*768 + e*512 + h] = acc[t];
    }
}

// ---------------------------------------------------------
// K3: hid = relu(cat @ W1^T + b1) -> fp16 hi/lo splits,
//     W1t staged via 3-stage cp.async ring.  grid (240,1,2)
// ---------------------------------------------------------
#define HCH 96
__global__ __launch_bounds__(256) void k_hid(const float* __restrict__ b1,
                                             const float* __restrict__ W2)
{
    if (blockIdx.z == 1){
        w2split_quads(W2, QA1, QTOT, blockIdx.x, 240);
        return;
    }
    __shared__ float cats[8*768];
    __shared__ float w1s[3][8*256];
    const int rb = blockIdx.x;
    const int o  = threadIdx.x;

    uint32_t w1dst[2];
    const float* w1src[2];
    #pragma unroll
    for (int it = 0; it < 2; it++){
        int seg = it*256 + o;
        int row = seg >> 6;
        int col4 = (seg & 63) * 4;
        w1dst[it] = smem_u32(&w1s[0][row*256 + col4]);
        w1src[it] = g_W1t + row*256 + col4;
    }

    #pragma unroll
    for (int c = 0; c < 2; c++){
        CP16(w1dst[0] + c*8192, w1src[0] + c*2048);
        CP16(w1dst[1] + c*8192, w1src[1] + c*2048);
        CP_COMMIT();
    }

    for (int i = o; i < 8*768; i += 256)
        cats[i] = g_cat[(size_t)rb*8*768 + i];
    __syncthreads();

    float acc[8];
    #pragma unroll
    for (int r=0;r<8;r++) acc[r]=0.f;

    for (int c = 0; c < HCH; c++){
        CP_WAIT1();
        __syncthreads();
        const int st = c % 3;

        if (c + 2 < HCH){
            const uint32_t so = (uint32_t)((c+2) % 3)*8192;
            CP16(w1dst[0] + so, w1src[0] + (c+2)*2048);
            CP16(w1dst[1] + so, w1src[1] + (c+2)*2048);
        }
        CP_COMMIT();

        #pragma unroll
        for (int ii = 0; ii < 8; ii++){
            float w = w1s[st][ii*256 + o];
            const int i = c*8 + ii;
            #pragma unroll
            for (int r=0;r<8;r++)
                acc[r] = fmaf(cats[r*768 + i], w, acc[r]);
        }
    }

    const float bb = b1[o];
    __syncthreads();
    #pragma unroll
    for (int r=0;r<8;r++)
        cats[r*256 + o] = fmaxf(acc[r] + bb, 0.f);
    __syncthreads();

    for (int idx = o; idx < 1024; idx += 256){
        int r = idx >> 7, p = idx & 127;
        float f0 = cats[r*256 + 2*p];
        float f1 = cats[r*256 + 2*p + 1];
        uint32_t hi, lo;
        split2(f0, f1, hi, lo);
        size_t gi = (size_t)(rb*8 + r)*128 + p;
        g_Ah[gi] = hi;
        g_Al[gi] = lo;
    }
}

// ---------------------------------------------------------
// K4: fp16x2-split mma.sync GEMM, 3-stage cp.async(.cg), 2 CTAs/SM.
//     Fragment loads software-pipelined within each chunk:
//     LDSM(ah,bh) -> cp.async next -> LDSM(al,bl) -> pass1(ah*bh)
//     -> pass2(al*bh) -> pass3(ah*bl).  al/bl latency hides
//     under pass1's 16 MMAs.
// ---------------------------------------------------------
#define KCH 16
#define ROWSTR 48
#define TILE_B   6144
#define STAGE_B  24576
#define OFF_BIAS (3*STAGE_B)
#define OFF_SM   (OFF_BIAS + 512)
#define OFF_SS   (OFF_SM + 1024)
#define OFF_SI   (OFF_SS + 1024)
#define GEMM_SMEM (OFF_SI + 1024)        // 77312

__global__ __launch_bounds__(256, 2) void k_gemm_fp16(const float* __restrict__ bias)
{
    extern __shared__ char sm[];
    const uint32_t smb = smem_u32(sm);
    float* bsm = (float*)(sm + OFF_BIAS);
    float* s_m = (float*)(sm + OFF_SM);
    float* s_s = (float*)(sm + OFF_SS);
    int*   s_i = (int*)  (sm + OFF_SI);

    const int tid  = threadIdx.x;
    const int lane = tid & 31;
    const int warp = tid >> 5;
    const int wm   = warp & 3;
    const int wn   = warp >> 2;
    const int tig  = lane & 3;
    const int g    = lane >> 2;
    const int m0   = blockIdx.x * 128;
    const int n0   = blockIdx.y * 128;

    if (tid < 128) bsm[tid] = (n0 + tid < VV) ? bias[n0 + tid] : 0.f;

    const int lr = tid >> 1;
    const int lh = tid & 1;
    const bool bval = (n0 + lr) < VV;
    const uint32_t* srcAh = g_Ah + (size_t)(m0 + lr)*128 + lh*4;
    const uint32_t* srcAl = g_Al + (size_t)(m0 + lr)*128 + lh*4;
    const uint32_t* srcBh = g_W2h + (bval ? (size_t)(n0 + lr)*128 : 0) + lh*4;
    const uint32_t* srcBl = g_W2l + (bval ? (size_t)(n0 + lr)*128 : 0) + lh*4;
    const uint32_t dA = smb + lr*ROWSTR + lh*16;
    const uint32_t dB = dA + 2*TILE_B;

    const uint32_t aAddr0 = smb + (wm*32 + (lane & 15))*ROWSTR + ((lane >> 4) << 4);
    uint32_t bAddr[4];
    {
        const uint32_t brow = wn*64 + ((lane >> 4) << 3) + (lane & 7);
        const uint32_t boff = ((lane >> 3) & 1) << 4;
        #pragma unroll
        for (int j = 0; j < 4; j++)
            bAddr[j] = smb + 2*TILE_B + (brow + j*16)*ROWSTR + boff;
    }

    float acc[2][8][4];
    #pragma unroll
    for (int i=0;i<2;i++)
        #pragma unroll
        for (int j=0;j<8;j++)
            #pragma unroll
            for (int t=0;t<4;t++) acc[i][j][t]=0.f;

    #pragma unroll
    for (int c = 0; c < 2; c++){
        const uint32_t so = c*STAGE_B;
        CP16(dA + so,          srcAh + c*8);
        CP16(dA + so + TILE_B, srcAl + c*8);
        CP16(dB + so,          srcBh + c*8);
        CP16(dB + so + TILE_B, srcBl + c*8);
        CP_COMMIT();
    }

    for (int c = 0; c < KCH; c++){
        const int st = c % 3;
        const uint32_t so = st*STAGE_B;
        CP_WAIT1();
        __syncthreads();

        uint32_t ah[2][4], al[2][4], bh[4][4], bl[4][4];
        // first batch: operands for pass 1
        #pragma unroll
        for (int i = 0; i < 2; i++)
            LDSM4(ah[i], aAddr0 + so + i*16*ROWSTR);
        #pragma unroll
        for (int j = 0; j < 4; j++)
            LDSM4(bh[j], bAddr[j] + so);

        // next chunk's loads in flight early
        if (c + 2 < KCH){
            const uint32_t so2 = (uint32_t)((c+2) % 3)*STAGE_B;
            CP16(dA + so2,          srcAh + (c+2)*8);
            CP16(dA + so2 + TILE_B, srcAl + (c+2)*8);
            CP16(dB + so2,          srcBh + (c+2)*8);
            CP16(dB + so2 + TILE_B, srcBl + (c+2)*8);
        }
        CP_COMMIT();

        // second batch: operands for passes 2/3 (latency hidden by pass 1)
        #pragma unroll
        for (int i = 0; i < 2; i++)
            LDSM4(al[i], aAddr0 + so + i*16*ROWSTR + TILE_B);
        #pragma unroll
        for (int j = 0; j < 4; j++)
            LDSM4(bl[j], bAddr[j] + so + TILE_B);

        // pass 1: ah * bh
        #pragma unroll
        for (int i = 0; i < 2; i++)
            #pragma unroll
            for (int j = 0; j < 8; j++)
                MMA16(acc[i][j], ah[i], &bh[j>>1][(j&1)*2]);
        // pass 2: al * bh
        #pragma unroll
        for (int i = 0; i < 2; i++)
            #pragma unroll
            for (int j = 0; j < 8; j++)
                MMA16(acc[i][j], al[i], &bh[j>>1][(j&1)*2]);
        // pass 3: ah * bl
        #pragma unroll
        for (int i = 0; i < 2; i++)
            #pragma unroll
            for (int j = 0; j < 8; j++)
                MMA16(acc[i][j], ah[i], &bl[j>>1][(j&1)*2]);
    }
    __syncthreads();

    // ---- epilogue: bias + relu + partial stats (fp32) + fp16 store ----
    #pragma unroll
    for (int i=0;i<2;i++){
        #pragma unroll
        for (int h=0;h<2;h++){
            const int r = wm*32 + i*16 + h*8 + g;
            float vv[16];
            float mx = -1e30f; int ai = 0x7fffffff;
            #pragma unroll
            for (int j=0;j<8;j++){
                #pragma unroll
                for (int t=0;t<2;t++){
                    int col = wn*64 + j*8 + 2*tig + t;
                    bool ok = (n0 + col) < VV;
                    float v = ok ? fmaxf(acc[i][j][h*2+t] + bsm[col], 0.f) : -1e30f;
                    vv[j*2+t] = v;
                    if (v > mx){ mx = v; ai = n0 + col; }
                }
            }
            #pragma unroll
            for (int msk=1; msk<=2; msk<<=1){
                float m2 = __shfl_xor_sync(0xffffffff, mx, msk);
                int   i2 = __shfl_xor_sync(0xffffffff, ai, msk);
                if (m2 > mx || (m2 == mx && i2 < ai)){ mx = m2; ai = i2; }
            }
            float s = 0.f;
            #pragma unroll
            for (int u=0;u<16;u++)
                s += (vv[u] > -1e29f) ? fexp(vv[u] - mx) : 0.f;
            #pragma unroll
            for (int msk=1; msk<=2; msk<<=1)
                s += __shfl_xor_sync(0xffffffff, s, msk);
            if (tig == 0){
                s_m[wn*128 + r] = mx; s_s[wn*128 + r] = s; s_i[wn*128 + r] = ai;
            }
            uint32_t* crow = g_C16 + (size_t)(m0 + r)*(VV/2) + n0/2;
            #pragma unroll
            for (int j=0;j<8;j++){
                int col = wn*64 + j*8 + 2*tig;
                if (n0 + col + 1 < VV){
                    half2 hv = __floats2half2_rn(vv[j*2], vv[j*2+1]);
                    crow[col/2] = *(uint32_t*)&hv;
                }
            }
        }
    }
    __syncthreads();
    if (tid < 128){
        float m1 = s_m[tid], m2 = s_m[128 + tid];
        float s1 = s_s[tid], s2 = s_s[128 + tid];
        int   i1 = s_i[tid], i2 = s_i[128 + tid];
        float mm = fmaxf(m1, m2);
        float ss = s1*fexps(m1-mm) + s2*fexps(m2-mm);
        int   ii = (m2 > m1 || (m2 == m1 && i2 < i1)) ? i2 : i1;
        int row = m0 + tid;
        g_pm[(size_t)row*NTILE + blockIdx.y] = mm;
        g_ps[(size_t)row*NTILE + blockIdx.y] = ss;
        g_pi[(size_t)row*NTILE + blockIdx.y] = ii;
    }
}

// ---------------------------------------------------------
// K5: fused stats + normalization. One block per row.
// ---------------------------------------------------------
__global__ __launch_bounds__(256) void k_norm(float* __restrict__ logp,
                                              float* __restrict__ seq)
{
    __shared__ float sm[256], ss[256];
    __shared__ int   si[256];
    __shared__ float sh_off;
    const int row = blockIdx.x;
    const int tid = threadIdx.x;

    float m = -1e30f, s = 0.f;
    int i = 0x7fffffff;
    for (int t = tid; t < NTILE; t += 256){
        float m2 = g_pm[(size_t)row*NTILE + t];
        float s2 = g_ps[(size_t)row*NTILE + t];
        int   i2 = g_pi[(size_t)row*NTILE + t];
        float mm = fmaxf(m, m2);
        s = s*fexps(m - mm) + s2*fexps(m2 - mm);
        i = (m2 > m || (m2 == m && i2 < i)) ? i2 : i;
        m = mm;
    }
    sm[tid]=m; ss[tid]=s; si[tid]=i;
    __syncthreads();
    for (int off = 128; off; off >>= 1){
        if (tid < off){
            float m1=sm[tid],     s1=ss[tid];     int i1=si[tid];
            float m2=sm[tid+off], s2=ss[tid+off]; int i2=si[tid+off];
            float mm = fmaxf(m1,m2);
            float sn = s1*fexps(m1-mm) + s2*fexps(m2-mm);
            int ia = (m2 > m1 || (m2 == m1 && i2 < i1)) ? i2 : i1;
            sm[tid]=mm; ss[tid]=sn; si[tid]=ia;
        }
        __syncthreads();
    }
    if (tid == 0){
        sh_off = sm[0] + logf(ss[0]);
        if (seq) seq[row] = (float)si[0];
    }
    __syncthreads();
    const float off = sh_off;

    const uint4* src = (const uint4*)(g_C16 + (size_t)row*(VV/2));
    float4* dst = (float4*)(logp + (size_t)row*VV);
    for (int idx = tid; idx < VV/8; idx += 256){
        uint4 v = __ldcs(src + idx);
        float2 a = __half22float2(*(half2*)&v.x);
        float2 b = __half22float2(*(half2*)&v.y);
        float2 c = __half22float2(*(half2*)&v.z);
        float2 d = __half22float2(*(half2*)&v.w);
        float4 o0 = make_float4(a.x - off, a.y - off, b.x - off, b.y - off);
        float4 o1 = make_float4(c.x - off, c.y - off, d.x - off, d.y - off);
        __stcs(dst + idx*2,     o0);
        __stcs(dst + idx*2 + 1, o1);
    }
}

// ---------------------------------------------------------
extern "C" void kernel_launch(void* const* d_in, const int* in_sizes, int n_in,
                              void* d_out, int out_size)
{
    const int*   ci   = (const int*)  d_in[1];
    const float* tok  = (const float*)d_in[2];
    const float* hc   = (const float*)d_in[3];
    const float* astp = (const float*)d_in[4];
    const float* wemb = (const float*)d_in[5];
    const float* Wih  = (const float*)d_in[6];
    const float* Whh  = (const float*)d_in[7];
    const float* bih  = (const float*)d_in[8];
    const float* bhh  = (const float*)d_in[9];
    const float* W1   = (const float*)d_in[10];
    const float* b1   = (const float*)d_in[11];
    const float* W2   = (const float*)d_in[12];
    const float* b2   = (const float*)d_in[13];

    float* out = (float*)d_out;
    long long off = (long long)out_size - (long long)ROWS*VV;
    if (off < 0) off = 0;
    float* logp = out + off;
    float* seq  = (off >= ROWS) ? out : nullptr;

    cudaFuncSetAttribute(k_gemm_fp16, cudaFuncAttributeMaxDynamicSharedMemorySize, GEMM_SMEM);

    k_prep<<<(3*NW + 255)/256, 256>>>(Wih, Whh, W1);
    k_dec<<<dim3(3, BB, 2), 256>>>(ci, hc, wemb, bih, bhh, W2);
    k_attn<<<dim3(6, BB, 2), 256>>>(tok, astp, W2);
    k_hid<<<dim3(ROWS/8, 1, 2), 256>>>(b1, W2);
    k_gemm_fp16<<<dim3(15, NTILE), 256, GEMM_SMEM>>>(b2);
    k_norm<<<ROWS, 256>>>(logp, seq);
}